// round 3
// baseline (speedup 1.0000x reference)
#include <cuda_runtime.h>
#include <cuda_bf16.h>
#include <math.h>

#define IMG_H 768
#define IMG_W 768
#define IMG_B 16
#define NPIXD 9437184.0
#define TILE_W 32
#define TILE_H 16
#define HALO 9
#define RAW_W 50
#define RAW_H 34            /* TILE_H + 2*HALO */
#define S_SZ (RAW_W*RAW_H)  /* 1700 */
#define H3_ROWS 34
#define H1_ROWS 22
#define BINS 4096
#define NACC 15

__device__ double       g_acc[NACC];
__device__ unsigned int g_hist[2*BINS];   /* [0..BINS): yp(body), [BINS..2BINS): x_i(body) */

/* Gaussian 1D weights (normalized, double-accurate, fp32 literals) */
#define G3_INIT {0.00147946f,0.00380425f,0.00875347f,0.01802342f,0.03320773f,\
                 0.05475029f,0.08077532f,0.10663899f,0.12597909f,0.13317599f,\
                 0.12597909f,0.10663899f,0.08077532f,0.05475029f,0.03320773f,\
                 0.01802342f,0.00875347f,0.00380425f,0.00147946f}
#define G1_INIT {0.00443305f,0.05400558f,0.24203624f,0.39905030f,0.24203624f,\
                 0.05400558f,0.00443305f}

/* ---------------- init: zero scratch ---------------- */
__global__ void k_init() {
    int i = blockIdx.x * 256 + threadIdx.x;
    if (i < 2*BINS) g_hist[i] = 0u;
    if (i < NACC)   g_acc[i]  = 0.0;
}

/* horizontal 19-tap segment: 4 consecutive outputs from a 22-float window */
__device__ __forceinline__ void h3seg(const float* __restrict__ s, float* __restrict__ d,
                                      int rr, int c0, const float* W19) {
    float w[22];
#pragma unroll
    for (int j = 0; j < 22; j++) w[j] = s[rr*RAW_W + c0 + j];
#pragma unroll
    for (int i = 0; i < 4; i++) {
        float a = 0.f;
#pragma unroll
        for (int k = 0; k < 19; k++) a = fmaf(w[i+k], W19[k], a);
        d[rr*32 + c0 + i] = a;
    }
}

/* horizontal 7-tap segment: raw row rr+6, center col offset +9 */
__device__ __forceinline__ void h1seg(const float* __restrict__ s, float* __restrict__ d,
                                      int rr, int c0, const float* W7) {
    float w[10];
#pragma unroll
    for (int j = 0; j < 10; j++) w[j] = s[(rr+6)*RAW_W + c0 + 6 + j];
#pragma unroll
    for (int i = 0; i < 4; i++) {
        float a = 0.f;
#pragma unroll
        for (int k = 0; k < 7; k++) a = fmaf(w[i+k], W7[k], a);
        d[rr*32 + c0 + i] = a;
    }
}

/* ---------------- mega kernel ---------------- */
__global__ void __launch_bounds__(256) k_main(
    const float* __restrict__ ypred, const float* __restrict__ npred,
    const float* __restrict__ xi,    const float* __restrict__ xmid,
    const float* __restrict__ wmap,  const float* __restrict__ nsyn)
{
    const float G3W[19] = G3_INIT;
    const float G1W[7]  = G1_INIT;

    __shared__ float s_xi[S_SZ], s_yp[S_SZ], s_xm[S_SZ];
    __shared__ float h3i[H3_ROWS*32], h3p[H3_ROWS*32], h3m[H3_ROWS*32];
    __shared__ float h1i[H1_ROWS*32], h1p[H1_ROWS*32];
    __shared__ double s_red[NACC];

    const int tid = threadIdx.x;
    if (tid < NACC) s_red[tid] = 0.0;

    const int gx0 = blockIdx.x * TILE_W;
    const int gy0 = blockIdx.y * TILE_H;
    const size_t base = (size_t)blockIdx.z * (IMG_H*IMG_W);

    /* load zero-padded halo tiles */
    for (int idx = tid; idx < S_SZ; idx += 256) {
        int r = idx / RAW_W, c = idx - r*RAW_W;
        int gy = gy0 + r - HALO, gx = gx0 + c - HALO;
        bool inb = ((unsigned)gy < IMG_H) && ((unsigned)gx < IMG_W);
        size_t g = base + (size_t)gy*IMG_W + gx;
        s_xi[idx] = inb ? xi[g]    : 0.f;
        s_yp[idx] = inb ? ypred[g] : 0.f;
        s_xm[idx] = inb ? xmid[g]  : 0.f;
    }
    __syncthreads();

    /* horizontal passes */
    for (int idx = tid; idx < H3_ROWS*8; idx += 256) {
        int rr = idx >> 3, c0 = (idx & 7) * 4;
        h3seg(s_xi, h3i, rr, c0, G3W);
        h3seg(s_yp, h3p, rr, c0, G3W);
        h3seg(s_xm, h3m, rr, c0, G3W);
    }
    for (int idx = tid; idx < H1_ROWS*8; idx += 256) {
        int rr = idx >> 3, c0 = (idx & 7) * 4;
        h1seg(s_xi, h1i, rr, c0, G1W);
        h1seg(s_yp, h1p, rr, c0, G1W);
    }
    __syncthreads();

    /* vertical + pointwise: thread = (col c, rows r0, r0+1) */
    const int c  = tid & 31;
    const int r0 = (tid >> 5) * 2;

    float li[2]={0,0}, lpv[2]={0,0}, lm[2]={0,0};
#pragma unroll
    for (int k = 0; k < 20; k++) {
        int o = (r0+k)*32 + c;
        float vi = h3i[o], vp = h3p[o], vm = h3m[o];
        if (k < 19) { li[0]=fmaf(vi,G3W[k],li[0]); lpv[0]=fmaf(vp,G3W[k],lpv[0]); lm[0]=fmaf(vm,G3W[k],lm[0]); }
        if (k > 0)  { li[1]=fmaf(vi,G3W[k-1],li[1]); lpv[1]=fmaf(vp,G3W[k-1],lpv[1]); lm[1]=fmaf(vm,G3W[k-1],lm[1]); }
    }
    float q1i[2]={0,0}, q1p[2]={0,0};
#pragma unroll
    for (int k = 0; k < 8; k++) {
        int o = (r0+k)*32 + c;
        float vi = h1i[o], vp = h1p[o];
        if (k < 7) { q1i[0]=fmaf(vi,G1W[k],q1i[0]); q1p[0]=fmaf(vp,G1W[k],q1p[0]); }
        if (k > 0) { q1i[1]=fmaf(vi,G1W[k-1],q1i[1]); q1p[1]=fmaf(vp,G1W[k-1],q1p[1]); }
    }

    /* 3x3 stencils from 4 raw rows (A=r0+8 .. D=r0+11) */
    const int b0 = (r0+9)*RAW_W + (c+9);
    float xa_m=s_xi[b0-RAW_W-1],  xa_0=s_xi[b0-RAW_W],   xa_p=s_xi[b0-RAW_W+1];
    float xb_m=s_xi[b0-1],        xb_0=s_xi[b0],         xb_p=s_xi[b0+1];
    float xc_m=s_xi[b0+RAW_W-1],  xc_0=s_xi[b0+RAW_W],   xc_p=s_xi[b0+RAW_W+1];
    float xd_m=s_xi[b0+2*RAW_W-1],xd_0=s_xi[b0+2*RAW_W], xd_p=s_xi[b0+2*RAW_W+1];
    float pa_m=s_yp[b0-RAW_W-1],  pa_0=s_yp[b0-RAW_W],   pa_p=s_yp[b0-RAW_W+1];
    float pb_m=s_yp[b0-1],        pb_0=s_yp[b0],         pb_p=s_yp[b0+1];
    float pc_m=s_yp[b0+RAW_W-1],  pc_0=s_yp[b0+RAW_W],   pc_p=s_yp[b0+RAW_W+1];
    float pd_m=s_yp[b0+2*RAW_W-1],pd_0=s_yp[b0+2*RAW_W], pd_p=s_yp[b0+2*RAW_W+1];

    float gxi_[2], gyi_[2], lapi_[2], gxp_[2], gyp_[2], lapp_[2], xcen[2], pcen[2];
    gxi_[0] = (xa_p-xa_m) + 2.f*(xb_p-xb_m) + (xc_p-xc_m);
    gyi_[0] = (xc_m-xa_m) + 2.f*(xc_0-xa_0) + (xc_p-xa_p);
    lapi_[0] = xa_0 + xc_0 + xb_m + xb_p - 4.f*xb_0;
    xcen[0] = xb_0;
    gxi_[1] = (xb_p-xb_m) + 2.f*(xc_p-xc_m) + (xd_p-xd_m);
    gyi_[1] = (xd_m-xb_m) + 2.f*(xd_0-xb_0) + (xd_p-xb_p);
    lapi_[1] = xb_0 + xd_0 + xc_m + xc_p - 4.f*xc_0;
    xcen[1] = xc_0;
    gxp_[0] = (pa_p-pa_m) + 2.f*(pb_p-pb_m) + (pc_p-pc_m);
    gyp_[0] = (pc_m-pa_m) + 2.f*(pc_0-pa_0) + (pc_p-pa_p);
    lapp_[0] = pa_0 + pc_0 + pb_m + pb_p - 4.f*pb_0;
    pcen[0] = pb_0;
    gxp_[1] = (pb_p-pb_m) + 2.f*(pc_p-pc_m) + (pd_p-pd_m);
    gyp_[1] = (pd_m-pb_m) + 2.f*(pd_0-pb_0) + (pd_p-pb_p);
    lapp_[1] = pb_0 + pd_0 + pc_m + pc_p - 4.f*pc_0;
    pcen[1] = pc_0;

    float a_rc=0.f,a_nb=0.f,a_sxi=0.f,a_syp=0.f,a_ex=0.f,a_ey=0.f;
    float a_ntex=0.f,a_tex=0.f,a_nf=0.f,a_hf=0.f,a_ic=0.f;
    float a_nfb=0.f,a_lf=0.f,a_mid=0.f,a_syn=0.f;

#pragma unroll
    for (int j = 0; j < 2; j++) {
        size_t g = base + (size_t)(gy0 + r0 + j)*IMG_W + (gx0 + c);
        float wv = wmap[g], nv = npred[g], sv = nsyn[g];
        float xv = xcen[j], pv = pcen[j];
        a_rc += fabsf(pv*wv - xv*wv);
        float gmi = sqrtf(fmaf(gxi_[j],gxi_[j], fmaf(gyi_[j],gyi_[j], 1e-8f)));
        float gmp = sqrtf(fmaf(gxp_[j],gxp_[j], fmaf(gyp_[j],gyp_[j], 1e-8f)));
        a_ex += fabsf(gxp_[j]-gxi_[j]);
        a_ey += fabsf(gyp_[j]-gyi_[j]);
        bool body = (xv > 0.15f) && (xv < 0.85f);
        bool flat = gmi < 0.03f;
        bool tex  = (gmi > 0.03f) && (gmi < 0.5f);
        if (body) {
            a_nb += 1.f; a_sxi += xv; a_syp += pv;
            int bp = (int)(pv * (float)BINS); bp = bp < 0 ? 0 : (bp > BINS-1 ? BINS-1 : bp);
            int bx = (int)(xv * (float)BINS); bx = bx < 0 ? 0 : (bx > BINS-1 ? BINS-1 : bx);
            atomicAdd(&g_hist[bp], 1u);
            atomicAdd(&g_hist[BINS + bx], 1u);
        }
        if (tex) { a_ntex += 1.f; a_tex += fabsf(gmp - gmi); }
        if (flat) {
            a_nf += 1.f;
            a_hf += fabsf(fabsf(lapp_[j]) - 0.3f*fabsf(lapi_[j]));
            a_ic += fmaxf(gmp - 2.0f*gmi, 0.f);
            if (body) {
                a_nfb += 1.f;
                a_lf  += fabsf((lpv[j]-lm[j]) - 0.3f*(li[j]-lm[j]));
                float mi = q1i[j]-li[j], mp = q1p[j]-lpv[j];
                a_mid += fabsf(fabsf(mp) - 0.3f*fabsf(mi));
                a_syn += fabsf(nv - sv);
            }
        }
    }

    /* reduce 15 accumulators: warp shuffle -> smem double -> global double */
    float vals[NACC] = {a_rc,a_nb,a_sxi,a_syp,a_ex,a_ey,a_ntex,a_tex,
                        a_nf,a_hf,a_ic,a_nfb,a_lf,a_mid,a_syn};
#pragma unroll
    for (int i = 0; i < NACC; i++) {
        float v = vals[i];
#pragma unroll
        for (int off = 16; off; off >>= 1) v += __shfl_down_sync(0xffffffffu, v, off);
        if ((tid & 31) == 0) atomicAdd(&s_red[i], (double)v);
    }
    __syncthreads();
    if (tid < NACC) atomicAdd(&g_acc[tid], s_red[tid]);
}

/* ---------------- finalize: quantiles + combine ---------------- */
__global__ void k_fin(float* __restrict__ out)
{
    __shared__ unsigned int pre_yp[257], pre_xi[257];
    __shared__ float qv[8];

    int t = threadIdx.x;
    unsigned int syp = 0, sxi = 0;
#pragma unroll
    for (int i = 0; i < 16; i++) {
        syp += g_hist[t*16 + i];
        sxi += g_hist[BINS + t*16 + i];
    }
    pre_yp[t] = syp; pre_xi[t] = sxi;
    if (t < 8) qv[t] = 0.f;
    __syncthreads();
    if (t == 0) {
        unsigned int run = 0;
        for (int i = 0; i < 256; i++) { unsigned int x = pre_yp[i]; pre_yp[i] = run; run += x; }
        pre_yp[256] = run;
        run = 0;
        for (int i = 0; i < 256; i++) { unsigned int x = pre_xi[i]; pre_xi[i] = run; run += x; }
        pre_xi[256] = run;
    }
    __syncthreads();

    long long n = (long long)pre_xi[256];
    float fr25 = 0.f, fr75 = 0.f;
    long long ranks[4] = {0,0,0,0};
    if (n > 0) {
        /* replicate reference fp32 rounding: pos = q * float(n-1) */
        float pos25 = 0.25f * (float)(n-1);
        float pos75 = 0.75f * (float)(n-1);
        fr25 = pos25 - floorf(pos25);
        fr75 = pos75 - floorf(pos75);
        ranks[0] = (long long)floorf(pos25);
        ranks[1] = (long long)ceilf(pos25);
        ranks[2] = (long long)floorf(pos75);
        ranks[3] = (long long)ceilf(pos75);
    }
    /* locate ranks: yp hist -> qv[0..3], xi hist -> qv[4..7] */
    {
        long long cum = (long long)pre_yp[t];
        for (int i = 0; i < 16; i++) {
            unsigned int cnt = g_hist[t*16 + i];
#pragma unroll
            for (int j = 0; j < 4; j++) {
                if (ranks[j] >= cum && ranks[j] < cum + (long long)cnt)
                    qv[j] = ((float)(t*16+i) + ((float)(ranks[j]-cum) + 0.5f)/(float)cnt) * (1.0f/(float)BINS);
            }
            cum += cnt;
        }
    }
    {
        long long cum = (long long)pre_xi[t];
        for (int i = 0; i < 16; i++) {
            unsigned int cnt = g_hist[BINS + t*16 + i];
#pragma unroll
            for (int j = 0; j < 4; j++) {
                if (ranks[j] >= cum && ranks[j] < cum + (long long)cnt)
                    qv[4+j] = ((float)(t*16+i) + ((float)(ranks[j]-cum) + 0.5f)/(float)cnt) * (1.0f/(float)BINS);
            }
            cum += cnt;
        }
    }
    __syncthreads();

    if (t == 0) {
        double nb      = g_acc[1];
        double rc      = g_acc[0] / NPIXD;
        double edge    = (g_acc[4] + g_acc[5]) / NPIXD;
        double mean_in = g_acc[2] / fmax(nb, 1.0);
        double mean_pr = g_acc[3] / fmax(nb, 1.0);
        float q25p = qv[0]*(1.f-fr25) + qv[1]*fr25;
        float q75p = qv[2]*(1.f-fr75) + qv[3]*fr75;
        float q25i = qv[4]*(1.f-fr25) + qv[5]*fr25;
        float q75i = qv[6]*(1.f-fr75) + qv[7]*fr75;
        double dm   = mean_pr - mean_in;
        double dq25 = (double)q25p - (double)q25i;
        double dq75 = (double)q75p - (double)q75i;
        double hu   = dm*dm + 0.5*(dq25*dq25 + dq75*dq75);
        double loss_hu  = (nb > 4096.0) ? hu : 0.0;
        double ntex = g_acc[6];
        double loss_tex = (ntex > 100.0) ? g_acc[7]/fmax(ntex,1.0) : 0.0;
        double nf   = g_acc[8];
        double loss_hf  = (nf > 100.0) ? g_acc[9]/fmax(nf,1.0)  : 0.0;
        double loss_ic  = (nf > 100.0) ? g_acc[10]/fmax(nf,1.0) : 0.0;
        double nfb  = g_acc[11];
        double loss_lf  = (nfb > 100.0) ? g_acc[12]/fmax(nfb,1.0) : 0.0;
        double loss_mid = (nfb > 100.0) ? g_acc[13]/fmax(nfb,1.0) : 0.0;
        double loss_syn = (nfb > 100.0) ? g_acc[14]/fmax(nfb,1.0) : 0.0;
        double total = 2.0*rc + 1.5*loss_hu + 1.0*edge + 0.8*loss_tex
                     + 1.5*loss_hf + 0.8*loss_mid + 0.6*loss_lf
                     + 1.0*loss_syn + 0.8*loss_ic;
        out[0] = (float)total;
    }
}

extern "C" void kernel_launch(void* const* d_in, const int* in_sizes, int n_in,
                              void* d_out, int out_size)
{
    (void)in_sizes; (void)n_in; (void)out_size;
    const float* ypred = (const float*)d_in[0];
    const float* npred = (const float*)d_in[1];
    const float* xi    = (const float*)d_in[2];
    /* d_in[3] = x_ip1 unused by the reference */
    const float* xmid  = (const float*)d_in[4];
    const float* wmap  = (const float*)d_in[5];
    const float* nsyn  = (const float*)d_in[6];

    k_init<<<32, 256>>>();
    dim3 grid(IMG_W/TILE_W, IMG_H/TILE_H, IMG_B);
    k_main<<<grid, 256>>>(ypred, npred, xi, xmid, wmap, nsyn);
    k_fin<<<1, 256>>>((float*)d_out);
}

// round 4
// speedup vs baseline: 1.0838x; 1.0838x over previous
#include <cuda_runtime.h>
#include <cuda_bf16.h>
#include <math.h>

#define IMG_H 768
#define IMG_W 768
#define IMG_B 16
#define NPIXD 9437184.0
#define TILE 32
#define RAW_W 53            /* cols gx0-12 .. gx0+40 */
#define RAW_H 50            /* rows gy0-9  .. gy0+40 */
#define H3STR 33
#define H1ROWS 38
#define BINS 4096
#define NACC 15
#define GRID_X 24
#define GRID_Y 24
#define NBLOCKS (GRID_X*GRID_Y*IMG_B)
#define SMEM_FLOATS 15408   /* 61632 bytes */

/* smem float offsets */
#define O_XI   0
#define O_YP   2650
#define O_XM   5300
#define O_H3I  7950
#define O_H3P  9600
#define O_H3M  11250
#define O_H1I  12900
#define O_H1P  14154

__device__ double       g_acc[NACC];
__device__ unsigned int g_hist[2*BINS];   /* [0,BINS)=yp(body)  [BINS,2BINS)=x_i(body) */
__device__ unsigned int g_done;

#define G3_INIT {0.00147946f,0.00380425f,0.00875347f,0.01802342f,0.03320773f,\
                 0.05475029f,0.08077532f,0.10663899f,0.12597909f,0.13317599f,\
                 0.12597909f,0.10663899f,0.08077532f,0.05475029f,0.03320773f,\
                 0.01802342f,0.00875347f,0.00380425f,0.00147946f}
#define G1_INIT {0.00443305f,0.05400558f,0.24203624f,0.39905030f,0.24203624f,\
                 0.05400558f,0.00443305f}

__global__ void __launch_bounds__(256, 3) k_main(
    const float* __restrict__ ypred, const float* __restrict__ npred,
    const float* __restrict__ xi,    const float* __restrict__ xmid,
    const float* __restrict__ wmap,  const float* __restrict__ nsyn,
    float* __restrict__ out)
{
    const float G3W[19] = G3_INIT;
    const float G1W[7]  = G1_INIT;

    extern __shared__ float sm[];
    float* s_xi = sm + O_XI;
    float* s_yp = sm + O_YP;
    float* s_xm = sm + O_XM;
    float* h3i  = sm + O_H3I;
    float* h3p  = sm + O_H3P;
    float* h3m  = sm + O_H3M;
    float* h1i  = sm + O_H1I;
    float* h1p  = sm + O_H1P;

    __shared__ double s_red[NACC];
    __shared__ unsigned int s_islast;

    const int tid = threadIdx.x;
    if (tid < NACC) s_red[tid] = 0.0;

    const int gx0 = blockIdx.x * TILE;
    const int gy0 = blockIdx.y * TILE;
    const size_t base = (size_t)blockIdx.z * (IMG_H*IMG_W);
    const bool xsafe = (blockIdx.x > 0) && (blockIdx.x < GRID_X-1);

    /* ---- load zero-padded halo tiles (float4 fast path for interior x) ---- */
    for (int idx = tid; idx < RAW_H*14; idx += 256) {
        int row = idx / 14, q = idx - row*14;
        int sc = q*4;
        int gy = gy0 + row - 9;
        float ai[4] = {0.f,0.f,0.f,0.f};
        float ap[4] = {0.f,0.f,0.f,0.f};
        float am[4] = {0.f,0.f,0.f,0.f};
        if ((unsigned)gy < IMG_H) {
            int gxs = gx0 - 12 + sc;
            size_t g = base + (size_t)gy*IMG_W + gxs;
            if (xsafe) {
                float4 vi = *(const float4*)(xi+g);
                float4 vp = *(const float4*)(ypred+g);
                float4 vm = *(const float4*)(xmid+g);
                ai[0]=vi.x; ai[1]=vi.y; ai[2]=vi.z; ai[3]=vi.w;
                ap[0]=vp.x; ap[1]=vp.y; ap[2]=vp.z; ap[3]=vp.w;
                am[0]=vm.x; am[1]=vm.y; am[2]=vm.z; am[3]=vm.w;
            } else {
#pragma unroll
                for (int e = 0; e < 4; e++) {
                    if ((unsigned)(gxs+e) < IMG_W) {
                        ai[e] = xi[g+e]; ap[e] = ypred[g+e]; am[e] = xmid[g+e];
                    }
                }
            }
        }
        int o = row*RAW_W + sc;
#pragma unroll
        for (int e = 0; e < 4; e++) {
            if (sc+e < RAW_W) { s_xi[o+e]=ai[e]; s_yp[o+e]=ap[e]; s_xm[o+e]=am[e]; }
        }
    }
    __syncthreads();

    /* ---- horizontal convs: thread = (row = tid&63, seg = tid>>6), 8 outputs ---- */
    {
        int row = tid & 63, seg = tid >> 6;
        if (row < RAW_H) {
            const int bi = row*RAW_W + seg*8 + 3;
            const int bo = row*H3STR + seg*8;
            float w[26];
#pragma unroll
            for (int j = 0; j < 26; j++) w[j] = s_xi[bi+j];
#pragma unroll
            for (int i = 0; i < 8; i++) {
                float a = 0.f;
#pragma unroll
                for (int k = 0; k < 19; k++) a = fmaf(w[i+k], G3W[k], a);
                h3i[bo+i] = a;
            }
#pragma unroll
            for (int j = 0; j < 26; j++) w[j] = s_yp[bi+j];
#pragma unroll
            for (int i = 0; i < 8; i++) {
                float a = 0.f;
#pragma unroll
                for (int k = 0; k < 19; k++) a = fmaf(w[i+k], G3W[k], a);
                h3p[bo+i] = a;
            }
#pragma unroll
            for (int j = 0; j < 26; j++) w[j] = s_xm[bi+j];
#pragma unroll
            for (int i = 0; i < 8; i++) {
                float a = 0.f;
#pragma unroll
                for (int k = 0; k < 19; k++) a = fmaf(w[i+k], G3W[k], a);
                h3m[bo+i] = a;
            }
        }
        if (row < H1ROWS) {
            const int bi = (row+6)*RAW_W + seg*8 + 9;
            const int bo = row*H3STR + seg*8;
            float u[14];
#pragma unroll
            for (int j = 0; j < 14; j++) u[j] = s_xi[bi+j];
#pragma unroll
            for (int i = 0; i < 8; i++) {
                float a = 0.f;
#pragma unroll
                for (int k = 0; k < 7; k++) a = fmaf(u[i+k], G1W[k], a);
                h1i[bo+i] = a;
            }
#pragma unroll
            for (int j = 0; j < 14; j++) u[j] = s_yp[bi+j];
#pragma unroll
            for (int i = 0; i < 8; i++) {
                float a = 0.f;
#pragma unroll
                for (int k = 0; k < 7; k++) a = fmaf(u[i+k], G1W[k], a);
                h1p[bo+i] = a;
            }
        }
    }
    __syncthreads();

    /* ---- vertical convs: thread = (col c, 4 rows r0..r0+3) ---- */
    const int c  = tid & 31;
    const int r0 = (tid >> 5) << 2;

    float li[4]={0,0,0,0}, lp4[4]={0,0,0,0}, lm4[4]={0,0,0,0};
#pragma unroll
    for (int k = 0; k < 22; k++) {
        int o = (r0+k)*H3STR + c;
        float vi = h3i[o], vp = h3p[o], vm = h3m[o];
#pragma unroll
        for (int j = 0; j < 4; j++) {
            int kk = k - j;
            if (kk >= 0 && kk < 19) {
                li[j]  = fmaf(vi, G3W[kk], li[j]);
                lp4[j] = fmaf(vp, G3W[kk], lp4[j]);
                lm4[j] = fmaf(vm, G3W[kk], lm4[j]);
            }
        }
    }
    float q1i[4]={0,0,0,0}, q1p[4]={0,0,0,0};
#pragma unroll
    for (int k = 0; k < 10; k++) {
        int o = (r0+k)*H3STR + c;
        float vi = h1i[o], vp = h1p[o];
#pragma unroll
        for (int j = 0; j < 4; j++) {
            int kk = k - j;
            if (kk >= 0 && kk < 7) {
                q1i[j] = fmaf(vi, G1W[kk], q1i[j]);
                q1p[j] = fmaf(vp, G1W[kk], q1p[j]);
            }
        }
    }

    /* ---- pointwise + stencils + reductions ---- */
    float a_rc=0.f,a_nb=0.f,a_sxi=0.f,a_syp=0.f,a_ex=0.f,a_ey=0.f;
    float a_ntex=0.f,a_tex=0.f,a_nf=0.f,a_hf=0.f,a_ic=0.f;
    float a_nfb=0.f,a_lf=0.f,a_mid=0.f,a_syn=0.f;

#pragma unroll
    for (int j = 0; j < 4; j++) {
        int p = (r0+j+9)*RAW_W + (c+12);
        float x00=s_xi[p-RAW_W-1], x01=s_xi[p-RAW_W], x02=s_xi[p-RAW_W+1];
        float x10=s_xi[p-1],       x11=s_xi[p],       x12=s_xi[p+1];
        float x20=s_xi[p+RAW_W-1], x21=s_xi[p+RAW_W], x22=s_xi[p+RAW_W+1];
        float y00=s_yp[p-RAW_W-1], y01=s_yp[p-RAW_W], y02=s_yp[p-RAW_W+1];
        float y10=s_yp[p-1],       y11=s_yp[p],       y12=s_yp[p+1];
        float y20=s_yp[p+RAW_W-1], y21=s_yp[p+RAW_W], y22=s_yp[p+RAW_W+1];

        float gxi_ = (x02-x00) + 2.f*(x12-x10) + (x22-x20);
        float gyi_ = (x20-x00) + 2.f*(x21-x01) + (x22-x02);
        float lapi = x01 + x21 + x10 + x12 - 4.f*x11;
        float gxp_ = (y02-y00) + 2.f*(y12-y10) + (y22-y20);
        float gyp_ = (y20-y00) + 2.f*(y21-y01) + (y22-y02);
        float lapp = y01 + y21 + y10 + y12 - 4.f*y11;
        float xv = x11, pv = y11;

        size_t g = base + (size_t)(gy0 + r0 + j)*IMG_W + (gx0 + c);
        float wv = wmap[g], nv = npred[g], sv = nsyn[g];

        a_rc += fabsf(pv*wv - xv*wv);
        float gmi = sqrtf(fmaf(gxi_,gxi_, fmaf(gyi_,gyi_, 1e-8f)));
        float gmp = sqrtf(fmaf(gxp_,gxp_, fmaf(gyp_,gyp_, 1e-8f)));
        a_ex += fabsf(gxp_-gxi_);
        a_ey += fabsf(gyp_-gyi_);
        bool body = (xv > 0.15f) && (xv < 0.85f);
        bool flat = gmi < 0.03f;
        bool tex  = (gmi > 0.03f) && (gmi < 0.5f);
        if (body) {
            a_nb += 1.f; a_sxi += xv; a_syp += pv;
            int bp = (int)(pv * (float)BINS); bp = bp < 0 ? 0 : (bp > BINS-1 ? BINS-1 : bp);
            int bx = (int)(xv * (float)BINS); bx = bx < 0 ? 0 : (bx > BINS-1 ? BINS-1 : bx);
            atomicAdd(&g_hist[bp], 1u);
            atomicAdd(&g_hist[BINS + bx], 1u);
        }
        if (tex) { a_ntex += 1.f; a_tex += fabsf(gmp - gmi); }
        if (flat) {
            a_nf += 1.f;
            a_hf += fabsf(fabsf(lapp) - 0.3f*fabsf(lapi));
            a_ic += fmaxf(gmp - 2.0f*gmi, 0.f);
            if (body) {
                a_nfb += 1.f;
                a_lf  += fabsf((lp4[j]-lm4[j]) - 0.3f*(li[j]-lm4[j]));
                float mi = q1i[j]-li[j], mp = q1p[j]-lp4[j];
                a_mid += fabsf(fabsf(mp) - 0.3f*fabsf(mi));
                a_syn += fabsf(nv - sv);
            }
        }
    }

    /* block reduction: warp shuffle -> smem double -> global double */
    {
        float vals[NACC] = {a_rc,a_nb,a_sxi,a_syp,a_ex,a_ey,a_ntex,a_tex,
                            a_nf,a_hf,a_ic,a_nfb,a_lf,a_mid,a_syn};
#pragma unroll
        for (int i = 0; i < NACC; i++) {
            float v = vals[i];
#pragma unroll
            for (int off = 16; off; off >>= 1) v += __shfl_down_sync(0xffffffffu, v, off);
            if ((tid & 31) == 0) atomicAdd(&s_red[i], (double)v);
        }
    }
    __syncthreads();
    if (tid < NACC) atomicAdd(&g_acc[tid], s_red[tid]);

    /* ---- last-block finalize ---- */
    __threadfence();
    if (tid == 0) {
        unsigned int prev = atomicAdd(&g_done, 1u);
        s_islast = (prev == NBLOCKS-1) ? 1u : 0u;
    }
    __syncthreads();
    if (!s_islast) return;
    __threadfence();

    {
        __shared__ unsigned int pre_yp[257], pre_xi2[257];
        __shared__ float qv[8];
        __shared__ float s_fr[2];
        const int t = tid;

        unsigned int syp = 0, sxi = 0;
#pragma unroll
        for (int i = 0; i < 16; i++) {
            syp += g_hist[t*16 + i];
            sxi += g_hist[BINS + t*16 + i];
        }
        pre_yp[t] = syp; pre_xi2[t] = sxi;
        if (t < 8) qv[t] = 0.f;
        __syncthreads();
        if (t == 0) {
            unsigned int run = 0;
            for (int i = 0; i < 256; i++) { unsigned int x = pre_yp[i]; pre_yp[i] = run; run += x; }
            pre_yp[256] = run;
            run = 0;
            for (int i = 0; i < 256; i++) { unsigned int x = pre_xi2[i]; pre_xi2[i] = run; run += x; }
            pre_xi2[256] = run;
        }
        __syncthreads();

        long long n = (long long)pre_xi2[256];
        long long ranks[4] = {0,0,0,0};
        float fr25 = 0.f, fr75 = 0.f;
        if (n > 0) {
            float pos25 = 0.25f * (float)(n-1);
            float pos75 = 0.75f * (float)(n-1);
            fr25 = pos25 - floorf(pos25);
            fr75 = pos75 - floorf(pos75);
            ranks[0] = (long long)floorf(pos25);
            ranks[1] = (long long)ceilf(pos25);
            ranks[2] = (long long)floorf(pos75);
            ranks[3] = (long long)ceilf(pos75);
        }
        if (t == 0) { s_fr[0] = fr25; s_fr[1] = fr75; }
        {
            long long cum = (long long)pre_yp[t];
            for (int i = 0; i < 16; i++) {
                unsigned int cnt = g_hist[t*16 + i];
#pragma unroll
                for (int j = 0; j < 4; j++) {
                    if (ranks[j] >= cum && ranks[j] < cum + (long long)cnt)
                        qv[j] = ((float)(t*16+i) + ((float)(ranks[j]-cum) + 0.5f)/(float)cnt) * (1.0f/(float)BINS);
                }
                cum += cnt;
            }
        }
        {
            long long cum = (long long)pre_xi2[t];
            for (int i = 0; i < 16; i++) {
                unsigned int cnt = g_hist[BINS + t*16 + i];
#pragma unroll
                for (int j = 0; j < 4; j++) {
                    if (ranks[j] >= cum && ranks[j] < cum + (long long)cnt)
                        qv[4+j] = ((float)(t*16+i) + ((float)(ranks[j]-cum) + 0.5f)/(float)cnt) * (1.0f/(float)BINS);
                }
                cum += cnt;
            }
        }
        __syncthreads();

        if (t == 0) {
            double nb      = g_acc[1];
            double rc      = g_acc[0] / NPIXD;
            double edge    = (g_acc[4] + g_acc[5]) / NPIXD;
            double mean_in = g_acc[2] / fmax(nb, 1.0);
            double mean_pr = g_acc[3] / fmax(nb, 1.0);
            float f25 = s_fr[0], f75 = s_fr[1];
            float q25p = qv[0]*(1.f-f25) + qv[1]*f25;
            float q75p = qv[2]*(1.f-f75) + qv[3]*f75;
            float q25i = qv[4]*(1.f-f25) + qv[5]*f25;
            float q75i = qv[6]*(1.f-f75) + qv[7]*f75;
            double dm   = mean_pr - mean_in;
            double dq25 = (double)q25p - (double)q25i;
            double dq75 = (double)q75p - (double)q75i;
            double hu   = dm*dm + 0.5*(dq25*dq25 + dq75*dq75);
            double loss_hu  = (nb > 4096.0) ? hu : 0.0;
            double ntex = g_acc[6];
            double loss_tex = (ntex > 100.0) ? g_acc[7]/fmax(ntex,1.0) : 0.0;
            double nf   = g_acc[8];
            double loss_hf  = (nf > 100.0) ? g_acc[9]/fmax(nf,1.0)  : 0.0;
            double loss_ic  = (nf > 100.0) ? g_acc[10]/fmax(nf,1.0) : 0.0;
            double nfb  = g_acc[11];
            double loss_lf  = (nfb > 100.0) ? g_acc[12]/fmax(nfb,1.0) : 0.0;
            double loss_mid = (nfb > 100.0) ? g_acc[13]/fmax(nfb,1.0) : 0.0;
            double loss_syn = (nfb > 100.0) ? g_acc[14]/fmax(nfb,1.0) : 0.0;
            double total = 2.0*rc + 1.5*loss_hu + 1.0*edge + 0.8*loss_tex
                         + 1.5*loss_hf + 0.8*loss_mid + 0.6*loss_lf
                         + 1.0*loss_syn + 0.8*loss_ic;
            out[0] = (float)total;
        }
        __syncthreads();

        /* self-clean for next graph replay */
        for (int i = t; i < 2*BINS; i += 256) g_hist[i] = 0u;
        if (t < NACC) g_acc[t] = 0.0;
        if (t == 0)  g_done = 0u;
    }
}

extern "C" void kernel_launch(void* const* d_in, const int* in_sizes, int n_in,
                              void* d_out, int out_size)
{
    (void)in_sizes; (void)n_in; (void)out_size;
    const float* ypred = (const float*)d_in[0];
    const float* npred = (const float*)d_in[1];
    const float* xi    = (const float*)d_in[2];
    /* d_in[3] = x_ip1 unused by the reference */
    const float* xmid  = (const float*)d_in[4];
    const float* wmap  = (const float*)d_in[5];
    const float* nsyn  = (const float*)d_in[6];

    cudaFuncSetAttribute(k_main, cudaFuncAttributeMaxDynamicSharedMemorySize,
                         SMEM_FLOATS * (int)sizeof(float));
    dim3 grid(GRID_X, GRID_Y, IMG_B);
    k_main<<<grid, 256, SMEM_FLOATS * sizeof(float)>>>(
        ypred, npred, xi, xmid, wmap, nsyn, (float*)d_out);
}